// round 11
// baseline (speedup 1.0000x reference)
#include <cuda_runtime.h>

#define BATCH 512
#define INF   1024
#define OUTF  64
#define INTER 32
#define NCOL  2048   // OUTF*INTER
#define OUTW  1088   // INF + OUTF

typedef unsigned long long ull;

// M scratch: 512 x 2048 fp32 = 4 MB (device global: allocation-free)
__device__ float g_M[BATCH * NCOL];

// ---------- packed f32x2 helpers (Blackwell sm_103a) ----------
__device__ __forceinline__ ull f2_add(ull a, ull b) {
    ull d; asm("add.rn.f32x2 %0, %1, %2;" : "=l"(d) : "l"(a), "l"(b)); return d;
}
__device__ __forceinline__ ull f2_fma(ull a, ull b, ull c) {
    ull d; asm("fma.rn.f32x2 %0, %1, %2, %3;" : "=l"(d) : "l"(a), "l"(b), "l"(c)); return d;
}
__device__ __forceinline__ ull f2_dup(float x) {
    ull r; asm("mov.b64 %0, {%1, %1};" : "=l"(r) : "f"(x)); return r;
}
__device__ __forceinline__ float f2_sum(ull a) {
    float lo, hi; asm("mov.b64 {%0, %1}, %2;" : "=f"(lo), "=f"(hi) : "l"(a));
    return lo + hi;
}

// ---------------- kernel 1: copy x into out[:, 0:1024] ----------------
__global__ void __launch_bounds__(256) copy_x_kernel(const float4* __restrict__ x,
                                                     float4* __restrict__ out) {
    int idx = blockIdx.x * 256 + threadIdx.x;     // 512*256 float4's
    int b = idx >> 8;
    int c = idx & 255;
    out[b * (OUTW / 4) + c] = x[idx];
}

// ---------------- kernel 2: GEMM  M = x @ W  (W = T reshaped [1024,2048]) --
// Block tile 64(M) x 128(N), BK=16, 256 threads, thread tile 4x8 via f32x2.
#define BM 64
#define BN 128
#define BK 16

__global__ void __launch_bounds__(256) gemm_kernel(const float* __restrict__ A,
                                                   const float* __restrict__ W) {
    __shared__ float As[BK][BM];   // transposed A tile
    __shared__ float Bs[BK][BN];

    const int tid = threadIdx.x;
    const int bm  = blockIdx.y * BM;
    const int bn  = blockIdx.x * BN;
    const int tidm = tid & 15;     // 16 threads along M (x4)
    const int tidn = tid >> 4;     // 16 threads along N (x8)

    ull acc[4][4];
#pragma unroll
    for (int m = 0; m < 4; ++m)
#pragma unroll
        for (int t = 0; t < 4; ++t) acc[m][t] = 0ull;   // packed (0.f, 0.f)

    // staging maps
    const int am = tid >> 2;              // 0..63
    const int ak = (tid & 3) * 4;         // 0,4,8,12
    const float* Aptr = A + (bm + am) * INF + ak;
    const int bk0 = tid >> 5;             // 0..7 (and +8)
    const int bn4 = (tid & 31) * 4;
    const float* Bptr = W + bn + bn4;

    for (int ks = 0; ks < INF; ks += BK) {
        float4 av  = *(const float4*)(Aptr + ks);
        float4 bv0 = *(const float4*)(Bptr + (ks + bk0) * NCOL);
        float4 bv1 = *(const float4*)(Bptr + (ks + bk0 + 8) * NCOL);
        __syncthreads();
        As[ak + 0][am] = av.x;
        As[ak + 1][am] = av.y;
        As[ak + 2][am] = av.z;
        As[ak + 3][am] = av.w;
        *(float4*)&Bs[bk0][bn4]     = bv0;
        *(float4*)&Bs[bk0 + 8][bn4] = bv1;
        __syncthreads();

#pragma unroll
        for (int kk = 0; kk < BK; ++kk) {
            ull ad[4];
#pragma unroll
            for (int m = 0; m < 4; ++m) ad[m] = f2_dup(As[kk][tidm * 4 + m]);
            const ull* brow = (const ull*)&Bs[kk][tidn * 8];
            ull b0 = brow[0], b1 = brow[1], b2 = brow[2], b3 = brow[3];
#pragma unroll
            for (int m = 0; m < 4; ++m) {
                acc[m][0] = f2_fma(ad[m], b0, acc[m][0]);
                acc[m][1] = f2_fma(ad[m], b1, acc[m][1]);
                acc[m][2] = f2_fma(ad[m], b2, acc[m][2]);
                acc[m][3] = f2_fma(ad[m], b3, acc[m][3]);
            }
        }
    }

    // epilogue: each acc[m][t] = 2 consecutive N columns
#pragma unroll
    for (int m = 0; m < 4; ++m) {
        int row = bm + tidm * 4 + m;
        ull* cp = (ull*)(g_M + row * NCOL + bn + tidn * 8);
#pragma unroll
        for (int t = 0; t < 4; ++t) cp[t] = acc[m][t];
    }
}

// ---------------- kernel 3: pairwise L1 + exp features ----------------
// grid (OUTF, BATCH/256), 256 threads; thread = one i, block owns one o.
__global__ void __launch_bounds__(256) dist_kernel(float* __restrict__ out) {
    __shared__ float Ms[256 * INTER];   // 32 KB: 256 rows of M[:, o, :]

    const int o   = blockIdx.x;
    const int tid = threadIdx.x;
    const int i   = blockIdx.y * 256 + tid;

    const ull ABS2 = 0x7FFFFFFF7FFFFFFFull;
    const ull NEG2 = 0x8000000080000000ull;

    // own row, pre-negated, packed f32x2 (32 floats = 16 packed regs)
    ull nmi[16];
    const ull* mrow = (const ull*)(g_M + i * NCOL + o * INTER);
#pragma unroll
    for (int t = 0; t < 16; ++t) nmi[t] = mrow[t] ^ NEG2;

    float feat = 0.0f;

    for (int jb = 0; jb < BATCH; jb += 256) {
        __syncthreads();
        // stage 256 rows (8 float4 per thread), fully coalesced
#pragma unroll
        for (int f = 0; f < 8; ++f) {
            int idx = tid + f * 256;          // float4 index 0..2047
            int r = idx >> 3, c = idx & 7;
            ((float4*)Ms)[idx] =
                *(const float4*)(g_M + (jb + r) * NCOL + o * INTER + c * 4);
        }
        __syncthreads();

        const ull* ms = (const ull*)Ms;
        for (int j = 0; j < 256; ++j) {
            const ull* mj = ms + j * 16;      // broadcast LDS (all lanes same j)

            // first 8 of 32 terms
            ull d0 = f2_add(nmi[0], mj[0]) & ABS2;
            ull d1 = f2_add(nmi[1], mj[1]) & ABS2;
            ull d2 = f2_add(nmi[2], mj[2]) & ABS2;
            ull d3 = f2_add(nmi[3], mj[3]) & ABS2;
            ull a0 = f2_add(d0, d1);
            ull a1 = f2_add(d2, d3);

            // provably exact early exit: partial > 105 for all lanes
            //   => full dist >= 105 => fp32 exp(-dist) == 0 bit-exactly
            float part = f2_sum(a0) + f2_sum(a1);
            if (__all_sync(0xFFFFFFFFu, part > 105.0f)) continue;

            // remaining 24 terms (two independent accumulator chains)
#pragma unroll
            for (int t = 4; t < 16; t += 2) {
                ull e0 = f2_add(nmi[t],     mj[t])     & ABS2;
                ull e1 = f2_add(nmi[t + 1], mj[t + 1]) & ABS2;
                a0 = f2_add(a0, e0);
                a1 = f2_add(a1, e1);
            }
            float dist = f2_sum(a0) + f2_sum(a1);
            feat += __expf(-dist);
        }
    }

    out[i * OUTW + INF + o] = feat;
}

extern "C" void kernel_launch(void* const* d_in, const int* in_sizes, int n_in,
                              void* d_out, int out_size) {
    const float* x = (const float*)d_in[0];
    const float* T = (const float*)d_in[1];
    // insurance against input-order surprises (sizes are distinct)
    if (in_sizes[0] == INF * OUTF * INTER && in_sizes[1] == BATCH * INF) {
        const float* tmp = x; x = T; T = tmp;
    }
    float* out = (float*)d_out;

    copy_x_kernel<<<BATCH, 256>>>((const float4*)x, (float4*)out);
    gemm_kernel<<<dim3(NCOL / BN, BATCH / BM), 256>>>(x, T);
    dist_kernel<<<dim3(OUTF, BATCH / 256), 256>>>(out);
}

// round 15
// speedup vs baseline: 2.2569x; 2.2569x over previous
#include <cuda_runtime.h>
#include <cuda_bf16.h>

typedef unsigned int       u32;
typedef unsigned long long u64;

#define BATCH 512
#define INF   1024
#define OUTF  64
#define INTER 32
#define NCOL  2048    // OUTF*INTER
#define OUTW  1088    // INF + OUTF

// M in bf16, packed bf16x2 per u32: 512 x 2048 bf16 = 2 MB
__device__ u32 g_Mb[BATCH * NCOL / 2];

// ======================= helpers =======================
__device__ __forceinline__ u32 smem_u32(const void* p) {
    u32 a;
    asm("{ .reg .u64 t; cvta.to.shared.u64 t, %1; cvt.u32.u64 %0, t; }" : "=r"(a) : "l"(p));
    return a;
}
__device__ __forceinline__ u32 pack_bf16(float lo, float hi) {
    u32 r; asm("cvt.rn.bf16x2.f32 %0, %1, %2;" : "=r"(r) : "f"(hi), "f"(lo)); return r;
}
__device__ __forceinline__ u32 badd2(u32 a, u32 b) {
    __nv_bfloat162 x = *reinterpret_cast<__nv_bfloat162*>(&a);
    __nv_bfloat162 y = *reinterpret_cast<__nv_bfloat162*>(&b);
    __nv_bfloat162 z = __hadd2(x, y);
    return *reinterpret_cast<u32*>(&z);
}
// |a + b| per bf16 half (b pre-negated by caller -> abs diff)
__device__ __forceinline__ u32 aab(u32 a, u32 b) { return badd2(a, b) & 0x7FFF7FFFu; }
// sum of the two bf16 halves in fp32 (bf16->f32 is exact)
__device__ __forceinline__ float bsum(u32 v) {
    return __uint_as_float(v << 16) + __uint_as_float(v & 0xFFFF0000u);
}
__device__ __forceinline__ void ldsm4(u32* r, u32 addr) {
    asm volatile("ldmatrix.sync.aligned.m8n8.x4.shared.b16 {%0,%1,%2,%3}, [%4];"
                 : "=r"(r[0]), "=r"(r[1]), "=r"(r[2]), "=r"(r[3]) : "r"(addr));
}
__device__ __forceinline__ void ldsm4t(u32* r, u32 addr) {
    asm volatile("ldmatrix.sync.aligned.m8n8.x4.trans.shared.b16 {%0,%1,%2,%3}, [%4];"
                 : "=r"(r[0]), "=r"(r[1]), "=r"(r[2]), "=r"(r[3]) : "r"(addr));
}
__device__ __forceinline__ void mma16816(float* d, const u32* a, u32 b0, u32 b1) {
    asm volatile(
        "mma.sync.aligned.m16n8k16.row.col.f32.bf16.bf16.f32 "
        "{%0,%1,%2,%3}, {%4,%5,%6,%7}, {%8,%9}, {%0,%1,%2,%3};"
        : "+f"(d[0]), "+f"(d[1]), "+f"(d[2]), "+f"(d[3])
        : "r"(a[0]), "r"(a[1]), "r"(a[2]), "r"(a[3]), "r"(b0), "r"(b1));
}

// ======================= kernel 1: copy x -> out[:, :1024] =======================
__global__ void __launch_bounds__(256) copy_x_kernel(const float4* __restrict__ x,
                                                     float4* __restrict__ out) {
    int idx = blockIdx.x * 256 + threadIdx.x;
    int b = idx >> 8;
    int c = idx & 255;
    out[b * (OUTW / 4) + c] = x[idx];
}

// ======================= kernel 2: bf16 mma.sync GEMM =======================
// Tile 128(M) x 128(N), K-step 32, 8 warps (warp tile 32m x 64n), double buffer.
// A smem pitch 80 B (64+16 pad), B smem pitch 272 B (256+16) -> conflict-free LDSM.
#define GTM 128
#define GTN 128
#define GTK 32
#define NK  (INF / GTK)   // 32
#define A_PITCH 80
#define B_PITCH 272

__global__ void __launch_bounds__(256) gemm_mma_kernel(const float* __restrict__ X,
                                                       const float* __restrict__ W) {
    __shared__ __align__(16) unsigned char As[2][GTM * A_PITCH];  // 2 x 10240
    __shared__ __align__(16) unsigned char Bs[2][GTK * B_PITCH];  // 2 x 8704

    const int tid  = threadIdx.x;
    const int lane = tid & 31;
    const int w    = tid >> 5;
    const int tn   = blockIdx.x * GTN;
    const int tm   = blockIdx.y * GTM;
    const int wm   = (w & 3) * 32;    // warp m-offset
    const int wn   = (w >> 2) * 64;   // warp n-offset

    float acc[2][8][4];
#pragma unroll
    for (int mf = 0; mf < 2; ++mf)
#pragma unroll
        for (int nf = 0; nf < 8; ++nf)
#pragma unroll
            for (int t = 0; t < 4; ++t) acc[mf][nf][t] = 0.0f;

    // staging maps (coalesced LDG.128)
    const int amg = tid >> 3, akq = tid & 7;    // A: 32 m-rows/iter, 8 float4 per row
    const int bkg = tid >> 5, bnq = tid & 31;   // B: 8 k-rows/iter, 32 float4 per row

    float4 af[4], bf[4];
#pragma unroll
    for (int it = 0; it < 4; ++it) {
        af[it] = *(const float4*)(X + (tm + amg + it * 32) * INF + akq * 4);
        bf[it] = *(const float4*)(W + (bkg + it * 8) * NCOL + tn + bnq * 4);
    }

#pragma unroll 1
    for (int c = 0; c < NK; ++c) {
        const int buf = c & 1;
        const u32 as_base = smem_u32(As[buf]);
        const u32 bs_base = smem_u32(Bs[buf]);

        // store staged regs (fp32 -> bf16) into current buffer
#pragma unroll
        for (int it = 0; it < 4; ++it) {
            u32 p0 = pack_bf16(af[it].x, af[it].y), p1 = pack_bf16(af[it].z, af[it].w);
            *(u64*)(&As[buf][(amg + it * 32) * A_PITCH + akq * 8]) = ((u64)p1 << 32) | p0;
            u32 q0 = pack_bf16(bf[it].x, bf[it].y), q1 = pack_bf16(bf[it].z, bf[it].w);
            *(u64*)(&Bs[buf][(bkg + it * 8) * B_PITCH + bnq * 8]) = ((u64)q1 << 32) | q0;
        }
        __syncthreads();

        // prefetch next chunk while computing this one
        if (c + 1 < NK) {
            const int ck = (c + 1) * GTK;
#pragma unroll
            for (int it = 0; it < 4; ++it) {
                af[it] = *(const float4*)(X + (tm + amg + it * 32) * INF + ck + akq * 4);
                bf[it] = *(const float4*)(W + (ck + bkg + it * 8) * NCOL + tn + bnq * 4);
            }
        }

        // A fragments: [k-half][m-frag]
        u32 a[2][2][4];
#pragma unroll
        for (int kh = 0; kh < 2; ++kh)
#pragma unroll
            for (int mf = 0; mf < 2; ++mf)
                ldsm4(a[kh][mf],
                      as_base + (u32)(wm + mf * 16 + (lane & 15)) * A_PITCH
                              + (u32)(kh * 32 + (lane >> 4) * 16));

        // B fragments in n-pairs; k16 x n16 per x4.trans
#pragma unroll
        for (int nf2 = 0; nf2 < 4; ++nf2) {
            u32 b0[4], b1[4];
            u32 ncol2 = (u32)(wn + nf2 * 16 + (lane >> 4) * 8) * 2;
            ldsm4t(b0, bs_base + (u32)(lane & 15) * B_PITCH + ncol2);
            ldsm4t(b1, bs_base + (u32)(16 + (lane & 15)) * B_PITCH + ncol2);
#pragma unroll
            for (int mf = 0; mf < 2; ++mf) {
                mma16816(acc[mf][nf2 * 2 + 0], a[0][mf], b0[0], b0[1]);
                mma16816(acc[mf][nf2 * 2 + 0], a[1][mf], b1[0], b1[1]);
                mma16816(acc[mf][nf2 * 2 + 1], a[0][mf], b0[2], b0[3]);
                mma16816(acc[mf][nf2 * 2 + 1], a[1][mf], b1[2], b1[3]);
            }
        }
        __syncthreads();
    }

    // epilogue: fp32 accum -> bf16x2 -> g_Mb
#pragma unroll
    for (int mf = 0; mf < 2; ++mf) {
        int r0 = tm + wm + mf * 16 + (lane >> 2);
#pragma unroll
        for (int nf = 0; nf < 8; ++nf) {
            int cc = (tn + wn + nf * 8 + (lane & 3) * 2) >> 1;
            g_Mb[r0 * (NCOL / 2) + cc]       = pack_bf16(acc[mf][nf][0], acc[mf][nf][1]);
            g_Mb[(r0 + 8) * (NCOL / 2) + cc] = pack_bf16(acc[mf][nf][2], acc[mf][nf][3]);
        }
    }
}

// ======================= kernel 3: pairwise L1 + exp =======================
// Group-sum lower bound gate: dist >= sum_g |G_i,g - G_j,g|  (triangle ineq.)
// Gate > 112 for all 32 lanes => true dist >= ~108 (3% bf16 slop) => exp
// contribution provably lost in the fp32 sum (diagonal term is 1.0). Skip exact.
__device__ __forceinline__ float gate_val(uint4 q, const u32* ng) {
    u32 a = badd2(aab(q.x, ng[0]), aab(q.y, ng[1]));
    u32 b = badd2(aab(q.z, ng[2]), aab(q.w, ng[3]));
    return bsum(badd2(a, b));
}
__device__ __forceinline__ float full_dist(const u32* mj, const u32* nm) {
    u32 t0 = badd2(aab(mj[0],  nm[0]),  aab(mj[1],  nm[1]));
    u32 t1 = badd2(aab(mj[2],  nm[2]),  aab(mj[3],  nm[3]));
    u32 t2 = badd2(aab(mj[4],  nm[4]),  aab(mj[5],  nm[5]));
    u32 t3 = badd2(aab(mj[6],  nm[6]),  aab(mj[7],  nm[7]));
    u32 t4 = badd2(aab(mj[8],  nm[8]),  aab(mj[9],  nm[9]));
    u32 t5 = badd2(aab(mj[10], nm[10]), aab(mj[11], nm[11]));
    u32 t6 = badd2(aab(mj[12], nm[12]), aab(mj[13], nm[13]));
    u32 t7 = badd2(aab(mj[14], nm[14]), aab(mj[15], nm[15]));
    u32 u0 = badd2(badd2(t0, t1), badd2(t2, t3));
    u32 u1 = badd2(badd2(t4, t5), badd2(t6, t7));
    return bsum(badd2(u0, u1));
}

__global__ void __launch_bounds__(256) dist_kernel(float* __restrict__ out) {
    __shared__ __align__(16) u32 Ms[BATCH * 16];  // 32 KB: all 512 rows, slice o
    __shared__ __align__(16) u32 Gs[BATCH * 4];   // 8 KB: 8 bf16 group sums/row

    const int o   = blockIdx.x;
    const int tid = threadIdx.x;
    const int i   = blockIdx.y * 256 + tid;

#pragma unroll
    for (int t = 0; t < 8; ++t) {
        int idx = tid + t * 256;                 // uint4 index 0..2047
        int r = idx >> 2, c = idx & 3;
        ((uint4*)Ms)[idx] = *(const uint4*)(g_Mb + r * (NCOL / 2) + o * (INTER / 2) + c * 4);
    }
    __syncthreads();

    // group sums (groups of 4 elements)
#pragma unroll
    for (int rr = 0; rr < 2; ++rr) {
        int r = tid + rr * 256;
        const u32* v = Ms + r * 16;
        float g[8];
#pragma unroll
        for (int t = 0; t < 8; ++t) g[t] = bsum(badd2(v[2 * t], v[2 * t + 1]));
        u32* gr = Gs + r * 4;
        gr[0] = pack_bf16(g[0], g[1]);
        gr[1] = pack_bf16(g[2], g[3]);
        gr[2] = pack_bf16(g[4], g[5]);
        gr[3] = pack_bf16(g[6], g[7]);
    }
    __syncthreads();

    u32 nm[16];
#pragma unroll
    for (int t = 0; t < 16; ++t) nm[t] = Ms[i * 16 + t] ^ 0x80008000u;
    u32 ng[4];
#pragma unroll
    for (int t = 0; t < 4; ++t) ng[t] = Gs[i * 4 + t] ^ 0x80008000u;

    float feat = 0.0f;

#pragma unroll 1
    for (int j = 0; j < BATCH; j += 4) {
        uint4 q0 = ((const uint4*)Gs)[j + 0];
        uint4 q1 = ((const uint4*)Gs)[j + 1];
        uint4 q2 = ((const uint4*)Gs)[j + 2];
        uint4 q3 = ((const uint4*)Gs)[j + 3];
        float p0 = gate_val(q0, ng);
        float p1 = gate_val(q1, ng);
        float p2 = gate_val(q2, ng);
        float p3 = gate_val(q3, ng);
        u32 s0 = __all_sync(0xFFFFFFFFu, p0 > 112.0f);
        u32 s1 = __all_sync(0xFFFFFFFFu, p1 > 112.0f);
        u32 s2 = __all_sync(0xFFFFFFFFu, p2 > 112.0f);
        u32 s3 = __all_sync(0xFFFFFFFFu, p3 > 112.0f);
        if (!s0) feat += __expf(-full_dist(Ms + (j + 0) * 16, nm));
        if (!s1) feat += __expf(-full_dist(Ms + (j + 1) * 16, nm));
        if (!s2) feat += __expf(-full_dist(Ms + (j + 2) * 16, nm));
        if (!s3) feat += __expf(-full_dist(Ms + (j + 3) * 16, nm));
    }

    out[i * OUTW + INF + o] = feat;
}

// ======================= launch =======================
extern "C" void kernel_launch(void* const* d_in, const int* in_sizes, int n_in,
                              void* d_out, int out_size) {
    const float* x = (const float*)d_in[0];
    const float* T = (const float*)d_in[1];
    if (in_sizes[0] == INF * OUTF * INTER && in_sizes[1] == BATCH * INF) {
        const float* tmp = x; x = T; T = tmp;
    }
    float* out = (float*)d_out;

    copy_x_kernel<<<BATCH, 256>>>((const float4*)x, (float4*)out);
    gemm_mma_kernel<<<dim3(NCOL / GTN, BATCH / GTM), 256>>>(x, T);
    dist_kernel<<<dim3(OUTF, BATCH / 256), 256>>>(out);
}

// round 16
// speedup vs baseline: 2.2681x; 1.0050x over previous
#include <cuda_runtime.h>
#include <cuda_bf16.h>

typedef unsigned int       u32;
typedef unsigned long long u64;

#define BATCH 512
#define INF   1024
#define OUTF  64
#define INTER 32
#define NCOL  2048    // OUTF*INTER
#define OUTW  1088    // INF + OUTF

// M in bf16, packed bf16x2 per u32: 512 x 2048 bf16 = 2 MB
__device__ u32 g_Mb[BATCH * NCOL / 2];

// ======================= helpers =======================
__device__ __forceinline__ u32 smem_u32(const void* p) {
    u32 a;
    asm("{ .reg .u64 t; cvta.to.shared.u64 t, %1; cvt.u32.u64 %0, t; }" : "=r"(a) : "l"(p));
    return a;
}
__device__ __forceinline__ u32 pack_bf16(float lo, float hi) {
    u32 r; asm("cvt.rn.bf16x2.f32 %0, %1, %2;" : "=r"(r) : "f"(hi), "f"(lo)); return r;
}
__device__ __forceinline__ u32 badd2(u32 a, u32 b) {
    __nv_bfloat162 x = *reinterpret_cast<__nv_bfloat162*>(&a);
    __nv_bfloat162 y = *reinterpret_cast<__nv_bfloat162*>(&b);
    __nv_bfloat162 z = __hadd2(x, y);
    return *reinterpret_cast<u32*>(&z);
}
// |a + b| per bf16 half (b pre-negated by caller -> abs diff)
__device__ __forceinline__ u32 aab(u32 a, u32 b) { return badd2(a, b) & 0x7FFF7FFFu; }
// sum of the two bf16 halves in fp32 (bf16->f32 is exact)
__device__ __forceinline__ float bsum(u32 v) {
    return __uint_as_float(v << 16) + __uint_as_float(v & 0xFFFF0000u);
}
__device__ __forceinline__ void ldsm4(u32* r, u32 addr) {
    asm volatile("ldmatrix.sync.aligned.m8n8.x4.shared.b16 {%0,%1,%2,%3}, [%4];"
                 : "=r"(r[0]), "=r"(r[1]), "=r"(r[2]), "=r"(r[3]) : "r"(addr));
}
__device__ __forceinline__ void ldsm4t(u32* r, u32 addr) {
    asm volatile("ldmatrix.sync.aligned.m8n8.x4.trans.shared.b16 {%0,%1,%2,%3}, [%4];"
                 : "=r"(r[0]), "=r"(r[1]), "=r"(r[2]), "=r"(r[3]) : "r"(addr));
}
__device__ __forceinline__ void mma16816(float* d, const u32* a, u32 b0, u32 b1) {
    asm volatile(
        "mma.sync.aligned.m16n8k16.row.col.f32.bf16.bf16.f32 "
        "{%0,%1,%2,%3}, {%4,%5,%6,%7}, {%8,%9}, {%0,%1,%2,%3};"
        : "+f"(d[0]), "+f"(d[1]), "+f"(d[2]), "+f"(d[3])
        : "r"(a[0]), "r"(a[1]), "r"(a[2]), "r"(a[3]), "r"(b0), "r"(b1));
}

// ======================= kernel 1: copy x -> out[:, :1024] =======================
__global__ void __launch_bounds__(256) copy_x_kernel(const float4* __restrict__ x,
                                                     float4* __restrict__ out) {
    int idx = blockIdx.x * 256 + threadIdx.x;
    int b = idx >> 8;
    int c = idx & 255;
    out[b * (OUTW / 4) + c] = x[idx];
}

// ======================= kernel 2: bf16 mma.sync GEMM =======================
// Tile 128(M) x 128(N), K-step 32, 8 warps (warp tile 32m x 64n), double buffer.
// A smem pitch 80 B (64+16 pad), B smem pitch 272 B (256+16) -> conflict-free LDSM.
#define GTM 128
#define GTN 128
#define GTK 32
#define NK  (INF / GTK)   // 32
#define A_PITCH 80
#define B_PITCH 272

__global__ void __launch_bounds__(256) gemm_mma_kernel(const float* __restrict__ X,
                                                       const float* __restrict__ W) {
    __shared__ __align__(16) unsigned char As[2][GTM * A_PITCH];  // 2 x 10240
    __shared__ __align__(16) unsigned char Bs[2][GTK * B_PITCH];  // 2 x 8704

    const int tid  = threadIdx.x;
    const int lane = tid & 31;
    const int w    = tid >> 5;
    const int tn   = blockIdx.x * GTN;
    const int tm   = blockIdx.y * GTM;
    const int wm   = (w & 3) * 32;    // warp m-offset
    const int wn   = (w >> 2) * 64;   // warp n-offset

    float acc[2][8][4];
#pragma unroll
    for (int mf = 0; mf < 2; ++mf)
#pragma unroll
        for (int nf = 0; nf < 8; ++nf)
#pragma unroll
            for (int t = 0; t < 4; ++t) acc[mf][nf][t] = 0.0f;

    // staging maps (coalesced LDG.128)
    const int amg = tid >> 3, akq = tid & 7;    // A: 32 m-rows/iter, 8 float4 per row
    const int bkg = tid >> 5, bnq = tid & 31;   // B: 8 k-rows/iter, 32 float4 per row

    float4 af[4], bf[4];
#pragma unroll
    for (int it = 0; it < 4; ++it) {
        af[it] = *(const float4*)(X + (tm + amg + it * 32) * INF + akq * 4);
        bf[it] = *(const float4*)(W + (bkg + it * 8) * NCOL + tn + bnq * 4);
    }

#pragma unroll 1
    for (int c = 0; c < NK; ++c) {
        const int buf = c & 1;
        const u32 as_base = smem_u32(As[buf]);
        const u32 bs_base = smem_u32(Bs[buf]);

        // store staged regs (fp32 -> bf16) into current buffer
#pragma unroll
        for (int it = 0; it < 4; ++it) {
            u32 p0 = pack_bf16(af[it].x, af[it].y), p1 = pack_bf16(af[it].z, af[it].w);
            *(u64*)(&As[buf][(amg + it * 32) * A_PITCH + akq * 8]) = ((u64)p1 << 32) | p0;
            u32 q0 = pack_bf16(bf[it].x, bf[it].y), q1 = pack_bf16(bf[it].z, bf[it].w);
            *(u64*)(&Bs[buf][(bkg + it * 8) * B_PITCH + bnq * 8]) = ((u64)q1 << 32) | q0;
        }
        __syncthreads();

        // prefetch next chunk while computing this one
        if (c + 1 < NK) {
            const int ck = (c + 1) * GTK;
#pragma unroll
            for (int it = 0; it < 4; ++it) {
                af[it] = *(const float4*)(X + (tm + amg + it * 32) * INF + ck + akq * 4);
                bf[it] = *(const float4*)(W + (ck + bkg + it * 8) * NCOL + tn + bnq * 4);
            }
        }

        // A fragments: [k-half][m-frag]
        u32 a[2][2][4];
#pragma unroll
        for (int kh = 0; kh < 2; ++kh)
#pragma unroll
            for (int mf = 0; mf < 2; ++mf)
                ldsm4(a[kh][mf],
                      as_base + (u32)(wm + mf * 16 + (lane & 15)) * A_PITCH
                              + (u32)(kh * 32 + (lane >> 4) * 16));

        // B fragments in n-pairs; k16 x n16 per x4.trans
#pragma unroll
        for (int nf2 = 0; nf2 < 4; ++nf2) {
            u32 b0[4], b1[4];
            u32 ncol2 = (u32)(wn + nf2 * 16 + (lane >> 4) * 8) * 2;
            ldsm4t(b0, bs_base + (u32)(lane & 15) * B_PITCH + ncol2);
            ldsm4t(b1, bs_base + (u32)(16 + (lane & 15)) * B_PITCH + ncol2);
#pragma unroll
            for (int mf = 0; mf < 2; ++mf) {
                mma16816(acc[mf][nf2 * 2 + 0], a[0][mf], b0[0], b0[1]);
                mma16816(acc[mf][nf2 * 2 + 0], a[1][mf], b1[0], b1[1]);
                mma16816(acc[mf][nf2 * 2 + 1], a[0][mf], b0[2], b0[3]);
                mma16816(acc[mf][nf2 * 2 + 1], a[1][mf], b1[2], b1[3]);
            }
        }
        __syncthreads();
    }

    // epilogue: fp32 accum -> bf16x2 -> g_Mb
#pragma unroll
    for (int mf = 0; mf < 2; ++mf) {
        int r0 = tm + wm + mf * 16 + (lane >> 2);
#pragma unroll
        for (int nf = 0; nf < 8; ++nf) {
            int cc = (tn + wn + nf * 8 + (lane & 3) * 2) >> 1;
            g_Mb[r0 * (NCOL / 2) + cc]       = pack_bf16(acc[mf][nf][0], acc[mf][nf][1]);
            g_Mb[(r0 + 8) * (NCOL / 2) + cc] = pack_bf16(acc[mf][nf][2], acc[mf][nf][3]);
        }
    }
}

// ======================= kernel 3: pairwise L1 + exp =======================
// Group-sum lower bound gate: dist >= sum_g |G_i,g - G_j,g|  (triangle ineq.)
// Gate > 112 for all 32 lanes => true dist >= ~108 (3% bf16 slop) => exp
// contribution provably lost in the fp32 sum (diagonal term is 1.0). Skip exact.
__device__ __forceinline__ float gate_val(uint4 q, const u32* ng) {
    u32 a = badd2(aab(q.x, ng[0]), aab(q.y, ng[1]));
    u32 b = badd2(aab(q.z, ng[2]), aab(q.w, ng[3]));
    return bsum(badd2(a, b));
}
__device__ __forceinline__ float full_dist(const u32* mj, const u32* nm) {
    u32 t0 = badd2(aab(mj[0],  nm[0]),  aab(mj[1],  nm[1]));
    u32 t1 = badd2(aab(mj[2],  nm[2]),  aab(mj[3],  nm[3]));
    u32 t2 = badd2(aab(mj[4],  nm[4]),  aab(mj[5],  nm[5]));
    u32 t3 = badd2(aab(mj[6],  nm[6]),  aab(mj[7],  nm[7]));
    u32 t4 = badd2(aab(mj[8],  nm[8]),  aab(mj[9],  nm[9]));
    u32 t5 = badd2(aab(mj[10], nm[10]), aab(mj[11], nm[11]));
    u32 t6 = badd2(aab(mj[12], nm[12]), aab(mj[13], nm[13]));
    u32 t7 = badd2(aab(mj[14], nm[14]), aab(mj[15], nm[15]));
    u32 u0 = badd2(badd2(t0, t1), badd2(t2, t3));
    u32 u1 = badd2(badd2(t4, t5), badd2(t6, t7));
    return bsum(badd2(u0, u1));
}

__global__ void __launch_bounds__(256) dist_kernel(float* __restrict__ out) {
    __shared__ __align__(16) u32 Ms[BATCH * 16];  // 32 KB: all 512 rows, slice o
    __shared__ __align__(16) u32 Gs[BATCH * 4];   // 8 KB: 8 bf16 group sums/row

    const int o   = blockIdx.x;
    const int tid = threadIdx.x;
    const int i   = blockIdx.y * 256 + tid;

#pragma unroll
    for (int t = 0; t < 8; ++t) {
        int idx = tid + t * 256;                 // uint4 index 0..2047
        int r = idx >> 2, c = idx & 3;
        ((uint4*)Ms)[idx] = *(const uint4*)(g_Mb + r * (NCOL / 2) + o * (INTER / 2) + c * 4);
    }
    __syncthreads();

    // group sums (groups of 4 elements)
#pragma unroll
    for (int rr = 0; rr < 2; ++rr) {
        int r = tid + rr * 256;
        const u32* v = Ms + r * 16;
        float g[8];
#pragma unroll
        for (int t = 0; t < 8; ++t) g[t] = bsum(badd2(v[2 * t], v[2 * t + 1]));
        u32* gr = Gs + r * 4;
        gr[0] = pack_bf16(g[0], g[1]);
        gr[1] = pack_bf16(g[2], g[3]);
        gr[2] = pack_bf16(g[4], g[5]);
        gr[3] = pack_bf16(g[6], g[7]);
    }
    __syncthreads();

    u32 nm[16];
#pragma unroll
    for (int t = 0; t < 16; ++t) nm[t] = Ms[i * 16 + t] ^ 0x80008000u;
    u32 ng[4];
#pragma unroll
    for (int t = 0; t < 4; ++t) ng[t] = Gs[i * 4 + t] ^ 0x80008000u;

    float feat = 0.0f;

#pragma unroll 1
    for (int j = 0; j < BATCH; j += 4) {
        uint4 q0 = ((const uint4*)Gs)[j + 0];
        uint4 q1 = ((const uint4*)Gs)[j + 1];
        uint4 q2 = ((const uint4*)Gs)[j + 2];
        uint4 q3 = ((const uint4*)Gs)[j + 3];
        float p0 = gate_val(q0, ng);
        float p1 = gate_val(q1, ng);
        float p2 = gate_val(q2, ng);
        float p3 = gate_val(q3, ng);
        u32 s0 = __all_sync(0xFFFFFFFFu, p0 > 112.0f);
        u32 s1 = __all_sync(0xFFFFFFFFu, p1 > 112.0f);
        u32 s2 = __all_sync(0xFFFFFFFFu, p2 > 112.0f);
        u32 s3 = __all_sync(0xFFFFFFFFu, p3 > 112.0f);
        if (!s0) feat += __expf(-full_dist(Ms + (j + 0) * 16, nm));
        if (!s1) feat += __expf(-full_dist(Ms + (j + 1) * 16, nm));
        if (!s2) feat += __expf(-full_dist(Ms + (j + 2) * 16, nm));
        if (!s3) feat += __expf(-full_dist(Ms + (j + 3) * 16, nm));
    }

    out[i * OUTW + INF + o] = feat;
}

// ======================= launch =======================
extern "C" void kernel_launch(void* const* d_in, const int* in_sizes, int n_in,
                              void* d_out, int out_size) {
    const float* x = (const float*)d_in[0];
    const float* T = (const float*)d_in[1];
    if (in_sizes[0] == INF * OUTF * INTER && in_sizes[1] == BATCH * INF) {
        const float* tmp = x; x = T; T = tmp;
    }
    float* out = (float*)d_out;

    copy_x_kernel<<<BATCH, 256>>>((const float4*)x, (float4*)out);
    gemm_mma_kernel<<<dim3(NCOL / GTN, BATCH / GTM), 256>>>(x, T);
    dist_kernel<<<dim3(OUTF, BATCH / 256), 256>>>(out);
}

// round 17
// speedup vs baseline: 2.8134x; 1.2404x over previous
#include <cuda_runtime.h>
#include <cuda_bf16.h>

typedef unsigned int       u32;
typedef unsigned long long u64;

#define BATCH 512
#define INF   1024
#define OUTF  64
#define INTER 32
#define NCOL  2048    // OUTF*INTER
#define OUTW  1088    // INF + OUTF

// M in bf16, packed bf16x2 per u32: 512 x 2048 bf16 = 2 MB
__device__ u32 g_Mb[BATCH * NCOL / 2];

// ======================= helpers =======================
__device__ __forceinline__ u32 smem_u32(const void* p) {
    u32 a;
    asm("{ .reg .u64 t; cvta.to.shared.u64 t, %1; cvt.u32.u64 %0, t; }" : "=r"(a) : "l"(p));
    return a;
}
__device__ __forceinline__ u32 pack_bf16(float lo, float hi) {
    u32 r; asm("cvt.rn.bf16x2.f32 %0, %1, %2;" : "=r"(r) : "f"(hi), "f"(lo)); return r;
}
__device__ __forceinline__ u32 badd2(u32 a, u32 b) {
    __nv_bfloat162 x = *reinterpret_cast<__nv_bfloat162*>(&a);
    __nv_bfloat162 y = *reinterpret_cast<__nv_bfloat162*>(&b);
    __nv_bfloat162 z = __hadd2(x, y);
    return *reinterpret_cast<u32*>(&z);
}
// |a + b| per bf16 half (b pre-negated by caller -> abs diff)
__device__ __forceinline__ u32 aab(u32 a, u32 b) { return badd2(a, b) & 0x7FFF7FFFu; }
// sum of the two bf16 halves in fp32 (bf16->f32 is exact)
__device__ __forceinline__ float bsum(u32 v) {
    return __uint_as_float(v << 16) + __uint_as_float(v & 0xFFFF0000u);
}
__device__ __forceinline__ void ldsm4(u32* r, u32 addr) {
    asm volatile("ldmatrix.sync.aligned.m8n8.x4.shared.b16 {%0,%1,%2,%3}, [%4];"
                 : "=r"(r[0]), "=r"(r[1]), "=r"(r[2]), "=r"(r[3]) : "r"(addr));
}
__device__ __forceinline__ void ldsm4t(u32* r, u32 addr) {
    asm volatile("ldmatrix.sync.aligned.m8n8.x4.trans.shared.b16 {%0,%1,%2,%3}, [%4];"
                 : "=r"(r[0]), "=r"(r[1]), "=r"(r[2]), "=r"(r[3]) : "r"(addr));
}
__device__ __forceinline__ void mma16816(float* d, const u32* a, u32 b0, u32 b1) {
    asm volatile(
        "mma.sync.aligned.m16n8k16.row.col.f32.bf16.bf16.f32 "
        "{%0,%1,%2,%3}, {%4,%5,%6,%7}, {%8,%9}, {%0,%1,%2,%3};"
        : "+f"(d[0]), "+f"(d[1]), "+f"(d[2]), "+f"(d[3])
        : "r"(a[0]), "r"(a[1]), "r"(a[2]), "r"(a[3]), "r"(b0), "r"(b1));
}

// ======================= kernel 1: bf16 mma.sync GEMM (+x copy) ==============
// Tile 64(M) x 128(N), K-step 32, 8 warps (warp tile 32m x 32n), double buffer.
// Grid = 16 x 8 = 128 CTAs (one wave over 148 SMs).
// The x -> out[:, :1024] copy is folded into the prologue (hides under MMA).
#define GTM 64
#define GTN 128
#define GTK 32
#define NK  (INF / GTK)   // 32
#define A_PITCH 80
#define B_PITCH 272

__global__ void __launch_bounds__(256) gemm_mma_kernel(const float* __restrict__ X,
                                                       const float* __restrict__ W,
                                                       float4* __restrict__ out) {
    __shared__ __align__(16) unsigned char As[2][GTM * A_PITCH];  // 2 x 5120
    __shared__ __align__(16) unsigned char Bs[2][GTK * B_PITCH];  // 2 x 8704

    const int tid  = threadIdx.x;
    const int lane = tid & 31;
    const int w    = tid >> 5;
    const int tn   = blockIdx.x * GTN;
    const int tm   = blockIdx.y * GTM;
    const int wm   = (w & 1) * 32;    // 2 warps along m
    const int wn   = (w >> 1) * 32;   // 4 warps along n

    // ---- folded copy: x -> out[:, :1024] (4 float4 per thread) ----
    {
        int cta = blockIdx.y * gridDim.x + blockIdx.x;      // 0..127
        int base = cta * 256 + tid;                          // 0..32767
#pragma unroll
        for (int t = 0; t < 4; ++t) {
            int idx = base + t * 32768;                      // 0..131071
            int b = idx >> 8, c = idx & 255;
            out[b * (OUTW / 4) + c] = ((const float4*)X)[idx];
        }
    }

    float acc[2][4][4];
#pragma unroll
    for (int mf = 0; mf < 2; ++mf)
#pragma unroll
        for (int nf = 0; nf < 4; ++nf)
#pragma unroll
            for (int t = 0; t < 4; ++t) acc[mf][nf][t] = 0.0f;

    // staging maps (coalesced LDG.128)
    const int amg = tid >> 3, akq = tid & 7;    // A: 32 m-rows/pass, 8 float4/row
    const int bkg = tid >> 5, bnq = tid & 31;   // B: 8 k-rows/pass, 32 float4/row

    float4 af[2], bf[4];
#pragma unroll
    for (int it = 0; it < 2; ++it)
        af[it] = *(const float4*)(X + (tm + amg + it * 32) * INF + akq * 4);
#pragma unroll
    for (int it = 0; it < 4; ++it)
        bf[it] = *(const float4*)(W + (bkg + it * 8) * NCOL + tn + bnq * 4);

#pragma unroll 1
    for (int c = 0; c < NK; ++c) {
        const int buf = c & 1;
        const u32 as_base = smem_u32(As[buf]);
        const u32 bs_base = smem_u32(Bs[buf]);

        // store staged regs (fp32 -> bf16) into current buffer
#pragma unroll
        for (int it = 0; it < 2; ++it) {
            u32 p0 = pack_bf16(af[it].x, af[it].y), p1 = pack_bf16(af[it].z, af[it].w);
            *(u64*)(&As[buf][(amg + it * 32) * A_PITCH + akq * 8]) = ((u64)p1 << 32) | p0;
        }
#pragma unroll
        for (int it = 0; it < 4; ++it) {
            u32 q0 = pack_bf16(bf[it].x, bf[it].y), q1 = pack_bf16(bf[it].z, bf[it].w);
            *(u64*)(&Bs[buf][(bkg + it * 8) * B_PITCH + bnq * 8]) = ((u64)q1 << 32) | q0;
        }
        __syncthreads();

        // prefetch next chunk (overlaps with MMA below)
        if (c + 1 < NK) {
            const int ck = (c + 1) * GTK;
#pragma unroll
            for (int it = 0; it < 2; ++it)
                af[it] = *(const float4*)(X + (tm + amg + it * 32) * INF + ck + akq * 4);
#pragma unroll
            for (int it = 0; it < 4; ++it)
                bf[it] = *(const float4*)(W + (ck + bkg + it * 8) * NCOL + tn + bnq * 4);
        }

        // A fragments: [k-half][m-frag]
        u32 a[2][2][4];
#pragma unroll
        for (int kh = 0; kh < 2; ++kh)
#pragma unroll
            for (int mf = 0; mf < 2; ++mf)
                ldsm4(a[kh][mf],
                      as_base + (u32)(wm + mf * 16 + (lane & 15)) * A_PITCH
                              + (u32)(kh * 32 + (lane >> 4) * 16));

        // B fragments in 16-wide n-pairs
#pragma unroll
        for (int nf2 = 0; nf2 < 2; ++nf2) {
            u32 b0[4], b1[4];
            u32 ncol2 = (u32)(wn + nf2 * 16 + (lane >> 4) * 8) * 2;
            ldsm4t(b0, bs_base + (u32)(lane & 15) * B_PITCH + ncol2);
            ldsm4t(b1, bs_base + (u32)(16 + (lane & 15)) * B_PITCH + ncol2);
#pragma unroll
            for (int mf = 0; mf < 2; ++mf) {
                mma16816(acc[mf][nf2 * 2 + 0], a[0][mf], b0[0], b0[1]);
                mma16816(acc[mf][nf2 * 2 + 0], a[1][mf], b1[0], b1[1]);
                mma16816(acc[mf][nf2 * 2 + 1], a[0][mf], b0[2], b0[3]);
                mma16816(acc[mf][nf2 * 2 + 1], a[1][mf], b1[2], b1[3]);
            }
        }
        // no trailing sync: next iter writes the OTHER buffer, and any warp
        // reading that buffer finished before it passed THIS iter's sync.
    }

    // epilogue: fp32 accum -> bf16x2 -> g_Mb
#pragma unroll
    for (int mf = 0; mf < 2; ++mf) {
        int r0 = tm + wm + mf * 16 + (lane >> 2);
#pragma unroll
        for (int nf = 0; nf < 4; ++nf) {
            int cc = (tn + wn + nf * 8 + (lane & 3) * 2) >> 1;
            g_Mb[r0 * (NCOL / 2) + cc]       = pack_bf16(acc[mf][nf][0], acc[mf][nf][1]);
            g_Mb[(r0 + 8) * (NCOL / 2) + cc] = pack_bf16(acc[mf][nf][2], acc[mf][nf][3]);
        }
    }
}

// ======================= kernel 2: pairwise L1 + exp =======================
// Group-sum lower bound gate: dist >= sum_g |G_i,g - G_j,g| (triangle ineq.)
// Gate > 112 for all lanes => contribution provably lost vs the 1.0 diagonal
// term at fp32 (and far below the 1e-3 rel tolerance). Skip is exact.
__device__ __forceinline__ float gate_val(uint4 q, const u32* ng) {
    u32 a = badd2(aab(q.x, ng[0]), aab(q.y, ng[1]));
    u32 b = badd2(aab(q.z, ng[2]), aab(q.w, ng[3]));
    return bsum(badd2(a, b));
}
__device__ __forceinline__ float full_dist(const u32* mj, const u32* nm) {
    u32 t0 = badd2(aab(mj[0],  nm[0]),  aab(mj[1],  nm[1]));
    u32 t1 = badd2(aab(mj[2],  nm[2]),  aab(mj[3],  nm[3]));
    u32 t2 = badd2(aab(mj[4],  nm[4]),  aab(mj[5],  nm[5]));
    u32 t3 = badd2(aab(mj[6],  nm[6]),  aab(mj[7],  nm[7]));
    u32 t4 = badd2(aab(mj[8],  nm[8]),  aab(mj[9],  nm[9]));
    u32 t5 = badd2(aab(mj[10], nm[10]), aab(mj[11], nm[11]));
    u32 t6 = badd2(aab(mj[12], nm[12]), aab(mj[13], nm[13]));
    u32 t7 = badd2(aab(mj[14], nm[14]), aab(mj[15], nm[15]));
    u32 u0 = badd2(badd2(t0, t1), badd2(t2, t3));
    u32 u1 = badd2(badd2(t4, t5), badd2(t6, t7));
    return bsum(badd2(u0, u1));
}

__global__ void __launch_bounds__(256) dist_kernel(float* __restrict__ out) {
    __shared__ __align__(16) u32 Ms[BATCH * 16];  // 32 KB: all 512 rows, slice o
    __shared__ __align__(16) u32 Gs[BATCH * 4];   // 8 KB: 8 bf16 group sums/row

    const int o   = blockIdx.x;
    const int tid = threadIdx.x;
    const int i   = blockIdx.y * 256 + tid;

#pragma unroll
    for (int t = 0; t < 8; ++t) {
        int idx = tid + t * 256;                 // uint4 index 0..2047
        int r = idx >> 2, c = idx & 3;
        ((uint4*)Ms)[idx] = *(const uint4*)(g_Mb + r * (NCOL / 2) + o * (INTER / 2) + c * 4);
    }
    __syncthreads();

    // group sums (groups of 4 elements)
#pragma unroll
    for (int rr = 0; rr < 2; ++rr) {
        int r = tid + rr * 256;
        const u32* v = Ms + r * 16;
        float g[8];
#pragma unroll
        for (int t = 0; t < 8; ++t) g[t] = bsum(badd2(v[2 * t], v[2 * t + 1]));
        u32* gr = Gs + r * 4;
        gr[0] = pack_bf16(g[0], g[1]);
        gr[1] = pack_bf16(g[2], g[3]);
        gr[2] = pack_bf16(g[4], g[5]);
        gr[3] = pack_bf16(g[6], g[7]);
    }
    __syncthreads();

    u32 nm[16];
#pragma unroll
    for (int t = 0; t < 16; ++t) nm[t] = Ms[i * 16 + t] ^ 0x80008000u;
    u32 ng[4];
#pragma unroll
    for (int t = 0; t < 4; ++t) ng[t] = Gs[i * 4 + t] ^ 0x80008000u;

    float feat = 0.0f;

#pragma unroll 1
    for (int j = 0; j < BATCH; j += 4) {
        uint4 q0 = ((const uint4*)Gs)[j + 0];
        uint4 q1 = ((const uint4*)Gs)[j + 1];
        uint4 q2 = ((const uint4*)Gs)[j + 2];
        uint4 q3 = ((const uint4*)Gs)[j + 3];
        float p0 = gate_val(q0, ng);
        float p1 = gate_val(q1, ng);
        float p2 = gate_val(q2, ng);
        float p3 = gate_val(q3, ng);
        float pmin = fminf(fminf(p0, p1), fminf(p2, p3));
        // single combined vote covers the (nearly always) all-pass case
        if (__all_sync(0xFFFFFFFFu, pmin > 112.0f)) continue;
        if (!__all_sync(0xFFFFFFFFu, p0 > 112.0f))
            feat += __expf(-full_dist(Ms + (j + 0) * 16, nm));
        if (!__all_sync(0xFFFFFFFFu, p1 > 112.0f))
            feat += __expf(-full_dist(Ms + (j + 1) * 16, nm));
        if (!__all_sync(0xFFFFFFFFu, p2 > 112.0f))
            feat += __expf(-full_dist(Ms + (j + 2) * 16, nm));
        if (!__all_sync(0xFFFFFFFFu, p3 > 112.0f))
            feat += __expf(-full_dist(Ms + (j + 3) * 16, nm));
    }

    out[i * OUTW + INF + o] = feat;
}

// ======================= launch =======================
extern "C" void kernel_launch(void* const* d_in, const int* in_sizes, int n_in,
                              void* d_out, int out_size) {
    const float* x = (const float*)d_in[0];
    const float* T = (const float*)d_in[1];
    if (in_sizes[0] == INF * OUTF * INTER && in_sizes[1] == BATCH * INF) {
        const float* tmp = x; x = T; T = tmp;
    }
    float* out = (float*)d_out;

    gemm_mma_kernel<<<dim3(NCOL / GTN, BATCH / GTM), 256>>>(x, T, (float4*)out);
    dist_kernel<<<dim3(OUTF, BATCH / 256), 256>>>(out);
}